// round 3
// baseline (speedup 1.0000x reference)
#include <cuda_runtime.h>
#include <cstdint>
#include <math.h>

#define Hdim 1024
#define Bq 64
#define Sq 512
#define NG 4096                 // 4*H
#define NROWS (Sq*Bq)           // 32768
#define HH (Hdim*Hdim)          // 1048576
#define WHOFF (2*4*HH)          // offset of rounded Wh inside g_Wr
#define NCTA 128

// ---------------- scratch (device globals; no allocations allowed) ----------------
__device__ float g_gx[(size_t)NROWS * NG];      // 512 MB: input-side gate pre-activations (+biases)
__device__ float g_seq[(size_t)Sq * Bq * Hdim]; // 128 MB: layer-0 hidden sequence [S][B][H]
__device__ float g_h[2][Bq * Hdim];             // final h per layer
__device__ float g_c[2][Bq * Hdim];             // final c per layer
__device__ float g_hbuf[2][Bq * Hdim];          // recurrent h double buffer
__device__ float g_Wr[2 * 2 * 4 * HH];          // tf32-rounded Wi (first half) and Wh (second half)
__device__ unsigned g_gen;                      // grid-barrier generation (monotonic)
__device__ unsigned g_cnt;                      // grid-barrier arrival counter (self-resetting)

// ---------------- helpers ----------------
__device__ __forceinline__ float f2tf32(float x) {
    uint32_t u;
    asm("cvt.rna.tf32.f32 %0, %1;" : "=r"(u) : "f"(x));
    return __uint_as_float(u);
}

__device__ __forceinline__ void mma_tf32(float d[4], const float a[4], const float b[2]) {
    const uint32_t* A = reinterpret_cast<const uint32_t*>(a);
    const uint32_t* B = reinterpret_cast<const uint32_t*>(b);
    asm volatile(
        "mma.sync.aligned.m16n8k8.row.col.f32.tf32.tf32.f32 "
        "{%0,%1,%2,%3}, {%4,%5,%6,%7}, {%8,%9}, {%0,%1,%2,%3};\n"
        : "+f"(d[0]), "+f"(d[1]), "+f"(d[2]), "+f"(d[3])
        : "r"(A[0]), "r"(A[1]), "r"(A[2]), "r"(A[3]),
          "r"(B[0]), "r"(B[1]));
}

__device__ __forceinline__ void cp16(void* dst, const void* src) {
    uint32_t d = (uint32_t)__cvta_generic_to_shared(dst);
    asm volatile("cp.async.cg.shared.global [%0], [%1], 16;\n" :: "r"(d), "l"(src));
}
#define CP_COMMIT() asm volatile("cp.async.commit_group;\n")
#define CP_WAIT0()  asm volatile("cp.async.wait_group 0;\n")
#define CP_WAIT1()  asm volatile("cp.async.wait_group 1;\n")

// software grid barrier (all-threads fence, tid0 arrive/spin). Generation is
// monotonic across barriers/launches/replays; each CTA reads the base at entry.
__device__ __forceinline__ void gridbar(unsigned target) {
    __threadfence();
    __syncthreads();
    if (threadIdx.x == 0) {
        unsigned old = atomicAdd(&g_cnt, 1);
        if (old == NCTA - 1) {
            g_cnt = 0;
            __threadfence();
            atomicAdd(&g_gen, 1);
        } else {
            while ((int)(*(volatile unsigned*)&g_gen - target) < 0) __nanosleep(32);
        }
        __threadfence();
    }
    __syncthreads();
}

// ---------------- prep: round weights to tf32 once ----------------
__global__ void prep_kernel(const float* __restrict__ Wi, const float* __restrict__ Wh) {
    size_t i = (size_t)blockIdx.x * 256 + threadIdx.x;  // grid covers 2*8388608
    const size_t half = (size_t)2 * 4 * HH;
    if (i < half)            g_Wr[i] = f2tf32(Wi[i]);
    else                     g_Wr[i] = f2tf32(Wh[i - half]);
}

// ---------------- projection GEMM: gx = X @ Wi[l] + (bi[l]+bh[l]) ----------------
__global__ void __launch_bounds__(256, 2)
proj_kernel(const float* __restrict__ xin, int layer,
            const float* __restrict__ bi_all, const float* __restrict__ bh_all) {
    __shared__ float As[2][128][20];
    __shared__ float Bs[2][16][68];

    const int tid = threadIdx.x;
    const int w = tid >> 5, lane = tid & 31;
    const int g = lane >> 2, t = lane & 3;
    const int wm = w & 3, wn = w >> 2;           // warp grid 4(M) x 2(N)
    const int rbase = blockIdx.y * 128;
    const int n0 = blockIdx.x * 64;
    const int gate = n0 >> 10;
    const int h0 = n0 & 1023;

    const float* Wr = g_Wr + (size_t)layer * 4 * HH + (size_t)gate * HH + h0;
    const float* Ag = (layer == 0) ? xin : g_seq;
    const float* bi = bi_all + layer * NG;
    const float* bh = bh_all + layer * NG;

    float acc[2][4][4];
#pragma unroll
    for (int i = 0; i < 2; i++)
#pragma unroll
        for (int j = 0; j < 4; j++)
#pragma unroll
            for (int k = 0; k < 4; k++) acc[i][j][k] = 0.f;

    auto loadA = [&](int buf, int kc) {
        int kb = kc * 16;
#pragma unroll
        for (int o = 0; o < 2; o++) {
            int idx = tid + o * 256;
            int r = idx >> 2, ch = idx & 3;
            int grow = rbase + r;
            const float* src;
            if (layer == 0) {
                int b = grow & 63, s = grow >> 6;
                src = Ag + ((size_t)b * Sq + s) * Hdim + kb + ch * 4;
            } else {
                src = Ag + (size_t)grow * Hdim + kb + ch * 4;
            }
            cp16(&As[buf][r][ch * 4], src);
        }
    };
    auto loadB = [&](int buf, int kc) {
        int kb = kc * 16;
        int r = tid >> 4, ch = tid & 15;
        cp16(&Bs[buf][r][ch * 4], Wr + (size_t)(kb + r) * Hdim + ch * 4);
    };

    loadA(0, 0); loadB(0, 0); CP_COMMIT();
    const int NKC = Hdim / 16;  // 64
    for (int kc = 0; kc < NKC; kc++) {
        CP_WAIT0();
        __syncthreads();
        int cur = kc & 1;
        if (kc + 1 < NKC) { loadA(cur ^ 1, kc + 1); loadB(cur ^ 1, kc + 1); CP_COMMIT(); }
#pragma unroll
        for (int ks = 0; ks < 2; ks++) {
            float a[2][4];
            float b[4][2];
#pragma unroll
            for (int mf = 0; mf < 2; mf++) {
                int m = wm * 32 + mf * 16;
                a[mf][0] = f2tf32(As[cur][m + g][ks * 8 + t]);
                a[mf][1] = f2tf32(As[cur][m + g + 8][ks * 8 + t]);
                a[mf][2] = f2tf32(As[cur][m + g][ks * 8 + t + 4]);
                a[mf][3] = f2tf32(As[cur][m + g + 8][ks * 8 + t + 4]);
            }
#pragma unroll
            for (int nf = 0; nf < 4; nf++) {
                int n = wn * 32 + nf * 8 + g;
                b[nf][0] = Bs[cur][ks * 8 + t][n];
                b[nf][1] = Bs[cur][ks * 8 + t + 4][n];
            }
#pragma unroll
            for (int mf = 0; mf < 2; mf++)
#pragma unroll
                for (int nf = 0; nf < 4; nf++)
                    mma_tf32(acc[mf][nf], a[mf], b[nf]);
        }
        __syncthreads();
    }

#pragma unroll
    for (int mf = 0; mf < 2; mf++) {
        int r0 = rbase + wm * 32 + mf * 16 + g;
#pragma unroll
        for (int nf = 0; nf < 4; nf++) {
            int nl = wn * 32 + nf * 8 + 2 * t;
            int ng = n0 + nl;
            float b0 = bi[ng] + bh[ng];
            float b1 = bi[ng + 1] + bh[ng + 1];
            g_gx[(size_t)r0 * NG + ng]           = acc[mf][nf][0] + b0;
            g_gx[(size_t)r0 * NG + ng + 1]       = acc[mf][nf][1] + b1;
            g_gx[(size_t)(r0 + 8) * NG + ng]     = acc[mf][nf][2] + b0;
            g_gx[(size_t)(r0 + 8) * NG + ng + 1] = acc[mf][nf][3] + b1;
        }
    }
}

// ---------------- persistent recurrent kernel: one launch per layer ----------------
// 128 CTAs, 256 threads. CTA owns h-columns [cta*8, cta*8+8) across all 4 gates
// (32 N-columns). Wh slice resident in SMEM (tf32), c-state resident in SMEM.
// Per step: pipelined load of h_t, 64x32x1024 tf32 MMA, fused cell update,
// h_{t+1} written tf32-rounded to global double buffer, grid barrier.
__global__ void __launch_bounds__(256, 1)
recur_kernel(int layer) {
    extern __shared__ float sm[];
    float* Bs  = sm;                        // [1024][36]  Wh slice (k-major, 32 cols)
    float* As  = Bs + 1024 * 36;            // [3][64][68] h staging (3-stage pipe)
    float* pre = As + 3 * 64 * 68;          // [64][33]    pre-activations
    float* gxs = pre + 64 * 33;             // [64][32]    gx staging
    float* cs  = gxs + 64 * 32;             // [64][8]     c-state

    const int tid = threadIdx.x;
    const int cta = blockIdx.x;
    const int lane = tid & 31, w = tid >> 5;
    const int g = lane >> 2, t4 = lane & 3;
    const int wm = w & 3, wn = w >> 2;      // warp grid 4(M) x 2(N), warp tile 16x16
    const int n0 = cta * 8;

    unsigned gen0 = *(volatile unsigned*)&g_gen;
    unsigned nb = 0;

    // zero c-state and this CTA's slice of the initial h buffer
    for (int i = tid; i < 512; i += 256) cs[i] = 0.f;
    for (int i = tid; i < 512; i += 256) {
        int b = i >> 3, j = i & 7;
        g_hbuf[0][b * 1024 + n0 + j] = 0.f;
    }

    // load Wh slice into SMEM: Bs[k][gate*8+j] (tf32-pre-rounded, no cvt later)
    const float* Whr = g_Wr + WHOFF + (size_t)layer * 4 * HH;
    for (int i = tid; i < 8192; i += 256) {
        int k = i >> 3, q = i & 7;
        int gate = q >> 1, hj = (q & 1) * 4;
        cp16(&Bs[k * 36 + gate * 8 + hj],
             Whr + (size_t)gate * HH + (size_t)k * 1024 + n0 + hj);
    }
    CP_COMMIT();

    gridbar(gen0 + (++nb));   // all h slices zeroed everywhere

    for (int t = 0; t < Sq; ++t) {
        const float* curh = g_hbuf[t & 1];
        float* nxth = g_hbuf[(t + 1) & 1];

        // prologue: gx + h chunk 0 (group), h chunk 1 (group)
        for (int i = tid; i < 512; i += 256) {
            int b = i >> 3, q = i & 7;
            int gate = q >> 1, hj = (q & 1) * 4;
            cp16(&gxs[b * 32 + gate * 8 + hj],
                 g_gx + ((size_t)(t * 64 + b)) * NG + (size_t)gate * 1024 + n0 + hj);
        }
        for (int i = tid; i < 1024; i += 256) {
            int r = i >> 4, c = i & 15;
            cp16(&As[0 * 64 * 68 + r * 68 + c * 4], curh + (size_t)r * 1024 + c * 4);
        }
        CP_COMMIT();
        for (int i = tid; i < 1024; i += 256) {
            int r = i >> 4, c = i & 15;
            cp16(&As[1 * 64 * 68 + r * 68 + c * 4], curh + (size_t)r * 1024 + 64 + c * 4);
        }
        CP_COMMIT();

        float acc[2][4];
#pragma unroll
        for (int a = 0; a < 2; a++)
#pragma unroll
            for (int b = 0; b < 4; b++) acc[a][b] = 0.f;

        const int NKC = 16;          // chunks of 64 over K=1024
        int buf = 0;
        for (int kc = 0; kc < NKC; ++kc) {
            if (kc + 1 < NKC) CP_WAIT1(); else CP_WAIT0();
            __syncthreads();
            if (kc + 2 < NKC) {
                int nbuf = buf + 2; if (nbuf >= 3) nbuf -= 3;
                int kb = (kc + 2) * 64;
                for (int i = tid; i < 1024; i += 256) {
                    int r = i >> 4, c = i & 15;
                    cp16(&As[nbuf * 64 * 68 + r * 68 + c * 4],
                         curh + (size_t)r * 1024 + kb + c * 4);
                }
                CP_COMMIT();
            }
            const float* Ab = As + buf * 64 * 68;
            const int m = wm * 16;
#pragma unroll
            for (int ks = 0; ks < 8; ++ks) {
                float a[4];
                a[0] = Ab[(m + g) * 68 + ks * 8 + t4];
                a[1] = Ab[(m + g + 8) * 68 + ks * 8 + t4];
                a[2] = Ab[(m + g) * 68 + ks * 8 + t4 + 4];
                a[3] = Ab[(m + g + 8) * 68 + ks * 8 + t4 + 4];
                const int kg = kc * 64 + ks * 8;
#pragma unroll
                for (int nf = 0; nf < 2; nf++) {
                    int n = wn * 16 + nf * 8 + g;
                    float b2[2];
                    b2[0] = Bs[(kg + t4) * 36 + n];
                    b2[1] = Bs[(kg + t4 + 4) * 36 + n];
                    mma_tf32(acc[nf], a, b2);
                }
            }
            buf++; if (buf >= 3) buf -= 3;
        }

        // stage pre-activations to SMEM
        {
            const int m = wm * 16;
#pragma unroll
            for (int nf = 0; nf < 2; nf++) {
                int col = wn * 16 + nf * 8 + 2 * t4;
                pre[(m + g) * 33 + col]         = acc[nf][0];
                pre[(m + g) * 33 + col + 1]     = acc[nf][1];
                pre[(m + g + 8) * 33 + col]     = acc[nf][2];
                pre[(m + g + 8) * 33 + col + 1] = acc[nf][3];
            }
        }
        __syncthreads();

        // fused cell update (h written tf32-rounded: feeds tf32 GEMMs; adds ~1e-4 rel)
        for (int p = tid; p < 512; p += 256) {
            int b = p >> 3, j = p & 7;
            float v0 = pre[b * 33 + j]      + gxs[b * 32 + j];
            float v1 = pre[b * 33 + 8 + j]  + gxs[b * 32 + 8 + j];
            float v2 = pre[b * 33 + 16 + j] + gxs[b * 32 + 16 + j];
            float v3 = pre[b * 33 + 24 + j] + gxs[b * 32 + 24 + j];
            float i_ = 1.f / (1.f + expf(-v0));
            float f_ = 1.f / (1.f + expf(-v1));
            float gg = tanhf(v2);
            float o_ = 1.f / (1.f + expf(-v3));
            float cn = f_ * cs[p] + i_ * gg;
            float hn = o_ * tanhf(cn);
            cs[p] = cn;
            float hnr = f2tf32(hn);
            nxth[b * 1024 + n0 + j] = hnr;
            if (layer == 0) g_seq[((size_t)t * 64 + b) * 1024 + n0 + j] = hnr;
            if (t == Sq - 1) {
                g_h[layer][b * 1024 + n0 + j] = hnr;
                g_c[layer][b * 1024 + n0 + j] = cn;
            }
        }
        gridbar(gen0 + (++nb));
    }
}

// ---------------- finalize: pack output tuple (seq_last, h_n[2], c_n[2]) ----------------
__global__ void finalize_kernel(float* __restrict__ out, int out_size) {
    int idx = blockIdx.x * 256 + threadIdx.x;  // 0..65535
    const int N1 = Bq * Hdim;
    if (idx + 0 * N1 < out_size) out[idx]          = g_h[1][idx];  // seq[:, -1, :]
    if (idx + 1 * N1 < out_size) out[idx + N1]     = g_h[0][idx];  // h_n layer 0
    if (idx + 2 * N1 < out_size) out[idx + 2 * N1] = g_h[1][idx];  // h_n layer 1
    if (idx + 3 * N1 < out_size) out[idx + 3 * N1] = g_c[0][idx];  // c_n layer 0
    if (idx + 4 * N1 < out_size) out[idx + 4 * N1] = g_c[1][idx];  // c_n layer 1
}

// ---------------- launch: 6 graph nodes total ----------------
extern "C" void kernel_launch(void* const* d_in, const int* in_sizes, int n_in,
                              void* d_out, int out_size) {
    const float* x  = (const float*)d_in[0];
    const float* Wi = (const float*)d_in[1];
    const float* bi = (const float*)d_in[2];
    const float* Wh = (const float*)d_in[3];
    const float* bh = (const float*)d_in[4];
    float* out = (float*)d_out;
    (void)in_sizes; (void)n_in;

    const int recur_smem = (1024 * 36 + 3 * 64 * 68 + 64 * 33 + 64 * 32 + 64 * 8) * 4;
    cudaFuncSetAttribute(recur_kernel, cudaFuncAttributeMaxDynamicSharedMemorySize,
                         recur_smem);

    prep_kernel<<<(2 * 2 * 4 * HH) / 256, 256>>>(Wi, Wh);
    for (int l = 0; l < 2; l++) {
        proj_kernel<<<dim3(NG / 64, NROWS / 128), 256>>>(x, l, bi, bh);
        recur_kernel<<<NCTA, 256, recur_smem>>>(l);
    }
    finalize_kernel<<<256, 256>>>(out, out_size);
}

// round 4
// speedup vs baseline: 1.4372x; 1.4372x over previous
#include <cuda_runtime.h>
#include <cuda_fp16.h>
#include <cstdint>
#include <math.h>

#define Hdim 1024
#define Bq 64
#define Sq 512
#define NG 4096                 // 4*H
#define NROWS (Sq*Bq)           // 32768
#define HH (Hdim*Hdim)          // 1048576
#define NCTA 128
#define WH16OFF ((size_t)2*4*HH)

// ---------------- scratch (device globals; no allocations allowed) ----------------
__device__ __half g_W16[(size_t)4 * 4 * HH];        // Wi (2 layers) then Wh (2 layers), [l][g][k][n]
__device__ __half g_x16[(size_t)Bq * Sq * Hdim];    // x converted to half, [b][s][k]
__device__ __half g_gx16[(size_t)NROWS * NG];       // input-side gate pre-activations (+biases)
__device__ __half g_seq16[(size_t)Sq * Bq * Hdim];  // layer-0 hidden sequence [S][B][H]
__device__ __half g_h16[2][Bq * Hdim];              // recurrent h double buffer (half)
__device__ float g_h[2][Bq * Hdim];                 // final h per layer (fp32)
__device__ float g_c[2][Bq * Hdim];                 // final c per layer (fp32)
__device__ unsigned g_flag[NCTA];                   // monotonic per-CTA step flags

// ---------------- helpers ----------------
__device__ __forceinline__ uint32_t sptr(const void* p) {
    return (uint32_t)__cvta_generic_to_shared(p);
}

__device__ __forceinline__ void mma_f16(float* d, const uint32_t* a, const uint32_t* b) {
    asm volatile(
        "mma.sync.aligned.m16n8k16.row.col.f32.f16.f16.f32 "
        "{%0,%1,%2,%3}, {%4,%5,%6,%7}, {%8,%9}, {%0,%1,%2,%3};\n"
        : "+f"(d[0]), "+f"(d[1]), "+f"(d[2]), "+f"(d[3])
        : "r"(a[0]), "r"(a[1]), "r"(a[2]), "r"(a[3]), "r"(b[0]), "r"(b[1]));
}

__device__ __forceinline__ void ldm_x4(uint32_t* r, uint32_t addr) {
    asm volatile("ldmatrix.sync.aligned.m8n8.x4.shared.b16 {%0,%1,%2,%3}, [%4];"
        : "=r"(r[0]), "=r"(r[1]), "=r"(r[2]), "=r"(r[3]) : "r"(addr));
}
__device__ __forceinline__ void ldm_x4t(uint32_t* r, uint32_t addr) {
    asm volatile("ldmatrix.sync.aligned.m8n8.x4.trans.shared.b16 {%0,%1,%2,%3}, [%4];"
        : "=r"(r[0]), "=r"(r[1]), "=r"(r[2]), "=r"(r[3]) : "r"(addr));
}

__device__ __forceinline__ void cp16(void* dst, const void* src) {
    uint32_t d = sptr(dst);
    asm volatile("cp.async.cg.shared.global [%0], [%1], 16;\n" :: "r"(d), "l"(src));
}
#define CP_COMMIT() asm volatile("cp.async.commit_group;\n")
#define CPW(n) asm volatile("cp.async.wait_group %0;\n" :: "n"(n))
__device__ __forceinline__ void cp_wait_n(int n) {
    switch (n) {
        case 0: CPW(0); break; case 1: CPW(1); break; case 2: CPW(2); break;
        case 3: CPW(3); break; case 4: CPW(4); break; case 5: CPW(5); break;
        case 6: CPW(6); break; default: CPW(7); break;
    }
}

// ---------------- prep: convert weights and x to half ----------------
__global__ void prep_kernel(const float* __restrict__ Wi, const float* __restrict__ Wh,
                            const float* __restrict__ x) {
    size_t i = (size_t)blockIdx.x * 256 + threadIdx.x;
    if (i < (size_t)2 * 4 * HH) {
        g_W16[i] = __float2half(Wi[i]);
        g_W16[WH16OFF + i] = __float2half(Wh[i]);
    }
    if (i < (size_t)Bq * Sq * Hdim) g_x16[i] = __float2half(x[i]);
}

// ---------------- projection GEMM: gx16 = X @ Wi[l] + (bi[l]+bh[l]) ----------------
// fp16 HMMA m16n8k16, CTA tile 128(M)x64(N), K chunks of 32, double-buffered.
// 8 warps as 4(M)x2(N), warp tile 32x32.
__global__ void __launch_bounds__(256, 3)
proj_kernel(int layer, const float* __restrict__ bi_all, const float* __restrict__ bh_all) {
    __shared__ __half As[2][128 * 40];   // pitch 40 halves = 80B (odd x16)
    __shared__ __half Bs[2][32 * 72];    // pitch 72 halves = 144B (odd x16)

    const int tid = threadIdx.x, lane = tid & 31, w = tid >> 5;
    const int g = lane >> 2, t4 = lane & 3;
    const int wm = w & 3, wn = w >> 2;
    const int rbase = blockIdx.y * 128;
    const int n0 = blockIdx.x * 64;
    const int gate = n0 >> 10, h0 = n0 & 1023;

    const __half* Wp = g_W16 + (size_t)layer * 4 * HH + (size_t)gate * HH + h0;
    const __half* Ap = (layer == 0) ? g_x16 : g_seq16;

    float acc[2][4][4];
#pragma unroll
    for (int a = 0; a < 2; a++)
#pragma unroll
        for (int b = 0; b < 4; b++)
#pragma unroll
            for (int c = 0; c < 4; c++) acc[a][b][c] = 0.f;

    auto loadA = [&](int buf, int kb) {
#pragma unroll
        for (int o = 0; o < 2; o++) {
            int idx = tid + o * 256;
            int r = idx >> 2, c = idx & 3;
            int grow = rbase + r;
            const __half* src;
            if (layer == 0) {
                int b = grow & 63, s = grow >> 6;
                src = Ap + ((size_t)b * Sq + s) * Hdim + kb + c * 8;
            } else {
                src = Ap + (size_t)grow * Hdim + kb + c * 8;
            }
            cp16(&As[buf][r * 40 + c * 8], src);
        }
    };
    auto loadB = [&](int buf, int kb) {
        int r = tid >> 3, c = tid & 7;
        cp16(&Bs[buf][r * 72 + c * 8], Wp + (size_t)(kb + r) * Hdim + c * 8);
    };

    loadA(0, 0); loadB(0, 0); CP_COMMIT();

    const int arow = lane & 15, aoff = (lane & 16) ? 8 : 0;
    const int NKC = Hdim / 32;  // 32
    for (int kc = 0; kc < NKC; kc++) {
        int cur = kc & 1;
        if (kc + 1 < NKC) {
            loadA(cur ^ 1, (kc + 1) * 32);
            loadB(cur ^ 1, (kc + 1) * 32);
            CP_COMMIT();
            CPW(1);
        } else {
            CPW(0);
        }
        __syncthreads();
        const __half* Ab = As[cur];
        const __half* Bb = Bs[cur];
#pragma unroll
        for (int ks2 = 0; ks2 < 2; ks2++) {
            uint32_t af[2][4], bf[2][4];
#pragma unroll
            for (int mt = 0; mt < 2; mt++)
                ldm_x4(af[mt], sptr(Ab + (wm * 32 + mt * 16 + arow) * 40 + ks2 * 16 + aoff));
#pragma unroll
            for (int nt = 0; nt < 2; nt++)
                ldm_x4t(bf[nt], sptr(Bb + (ks2 * 16 + arow) * 72 + wn * 32 + nt * 16 + aoff));
#pragma unroll
            for (int mt = 0; mt < 2; mt++)
#pragma unroll
                for (int q = 0; q < 4; q++)
                    mma_f16(acc[mt][q], af[mt], &bf[q >> 1][(q & 1) * 2]);
        }
        __syncthreads();
    }

    // epilogue: add (bi + bh), store half2
    const float* bi = bi_all + layer * NG;
    const float* bh = bh_all + layer * NG;
#pragma unroll
    for (int mt = 0; mt < 2; mt++) {
        int r0 = rbase + wm * 32 + mt * 16 + g;
#pragma unroll
        for (int q = 0; q < 4; q++) {
            int ng = n0 + wn * 32 + q * 8 + 2 * t4;
            float b0 = bi[ng] + bh[ng];
            float b1 = bi[ng + 1] + bh[ng + 1];
            *reinterpret_cast<__half2*>(g_gx16 + (size_t)r0 * NG + ng) =
                __floats2half2_rn(acc[mt][q][0] + b0, acc[mt][q][1] + b1);
            *reinterpret_cast<__half2*>(g_gx16 + (size_t)(r0 + 8) * NG + ng) =
                __floats2half2_rn(acc[mt][q][2] + b0, acc[mt][q][3] + b1);
        }
    }
}

// ---------------- persistent recurrent kernel: one launch per layer ----------------
// 128 CTAs x 256 threads. CTA owns h-cols [cta*8, cta*8+8) x 4 gates = 32 N cols.
// Wh slice (half) resident in SMEM (80KB); full h_t (132KB) staged per step.
// Producer/consumer flags instead of grid barrier.
__global__ void __launch_bounds__(256, 1)
recur_kernel(int layer) {
    extern __shared__ unsigned char smraw[];
    __half* Bs  = (__half*)smraw;                       // [1024][40]  Wh slice
    __half* As  = (__half*)(smraw + 81920);             // [64][1032]  full h staging
    float*  pre = (float*)(smraw + 81920 + 132096);     // [64][33]    pre-activations
    __half* gxs = (__half*)((char*)pre + 8448);         // [64][32]    gx staging
    float*  cs  = (float*)((char*)gxs + 4096);          // [512]       c-state

    const int tid = threadIdx.x, cta = blockIdx.x;
    const int lane = tid & 31, w = tid >> 5;
    const int g = lane >> 2, t4 = lane & 3;
    const int wm = w & 3, wn = w >> 2;     // warp grid 4(M) x 2(N), warp tile 16x16
    const int n0 = cta * 8;
    const int arow = lane & 15, aoff = (lane & 16) ? 8 : 0;

    unsigned F0 = *(volatile unsigned*)&g_flag[cta];   // own flag; all equal at entry

    // load Wh slice into SMEM: Bs[k][gate*8+j], half, k-major rows
    const __half* Whp = g_W16 + WH16OFF + (size_t)layer * 4 * HH;
    for (int i = tid; i < 4096; i += 256) {
        int k = i >> 2, gt = i & 3;
        cp16(&Bs[k * 40 + gt * 8], Whp + (size_t)gt * HH + (size_t)k * Hdim + n0);
    }
    CP_COMMIT();

    for (int i = tid; i < 512; i += 256) cs[i] = 0.f;
    if (tid < 64)   // zero own slice of h buffer 0 (16B per row)
        *reinterpret_cast<uint4*>(&g_h16[0][tid * Hdim + n0]) = make_uint4(0, 0, 0, 0);
    __threadfence();
    __syncthreads();
    if (tid == 0) *(volatile unsigned*)&g_flag[cta] = F0 + 1;

    for (int t = 0; t < Sq; t++) {
        // wait: all CTAs produced h for step t (or zero-init for t=0)
        unsigned need = F0 + 1 + t;
        if (tid < NCTA) {
            volatile unsigned* f = &g_flag[tid];
            while ((int)(*f - need) < 0) __nanosleep(20);
        }
        __threadfence();
        __syncthreads();

        const __half* curh = g_h16[t & 1];
        __half* nxth = g_h16[(t + 1) & 1];

        // gx staging (goes into first commit group)
        {
            int r = tid >> 2, gt = tid & 3;
            cp16(&gxs[r * 32 + gt * 8],
                 g_gx16 + ((size_t)(t * 64 + r)) * NG + (size_t)gt * 1024 + n0);
        }
        // stage the whole h (16 chunks of 64 k-cols), 8 commit groups of 2 chunks
#pragma unroll
        for (int kp = 0; kp < 8; kp++) {
#pragma unroll
            for (int kh = 0; kh < 2; kh++) {
                int kc = kp * 2 + kh;
#pragma unroll
                for (int o = 0; o < 2; o++) {
                    int idx = tid + o * 256;
                    int r = idx >> 3, c = idx & 7;
                    cp16(&As[r * 1032 + kc * 64 + c * 8],
                         curh + (size_t)r * Hdim + kc * 64 + c * 8);
                }
            }
            CP_COMMIT();
        }

        float acc[2][4];
#pragma unroll
        for (int a = 0; a < 2; a++)
#pragma unroll
            for (int b = 0; b < 4; b++) acc[a][b] = 0.f;

#pragma unroll
        for (int kc = 0; kc < 16; kc++) {
            cp_wait_n(7 - (kc >> 1));
            __syncthreads();
#pragma unroll
            for (int ks2 = 0; ks2 < 4; ks2++) {
                uint32_t af[4], bf[4];
                ldm_x4(af, sptr(As + (wm * 16 + arow) * 1032 + kc * 64 + ks2 * 16 + aoff));
                ldm_x4t(bf, sptr(Bs + (kc * 64 + ks2 * 16 + arow) * 40 + wn * 16 + aoff));
                mma_f16(acc[0], af, bf);
                mma_f16(acc[1], af, bf + 2);
            }
        }

        // stage pre-activations
#pragma unroll
        for (int nf = 0; nf < 2; nf++) {
            int col = wn * 16 + nf * 8 + 2 * t4;
            pre[(wm * 16 + g) * 33 + col]         = acc[nf][0];
            pre[(wm * 16 + g) * 33 + col + 1]     = acc[nf][1];
            pre[(wm * 16 + g + 8) * 33 + col]     = acc[nf][2];
            pre[(wm * 16 + g + 8) * 33 + col + 1] = acc[nf][3];
        }
        __syncthreads();

        // fused cell update
#pragma unroll
        for (int p = tid; p < 512; p += 256) {
            int b = p >> 3, j = p & 7;
            float v0 = pre[b * 33 + j]      + __half2float(gxs[b * 32 + j]);
            float v1 = pre[b * 33 + 8 + j]  + __half2float(gxs[b * 32 + 8 + j]);
            float v2 = pre[b * 33 + 16 + j] + __half2float(gxs[b * 32 + 16 + j]);
            float v3 = pre[b * 33 + 24 + j] + __half2float(gxs[b * 32 + 24 + j]);
            float i_ = 1.f / (1.f + expf(-v0));
            float f_ = 1.f / (1.f + expf(-v1));
            float gg = tanhf(v2);
            float o_ = 1.f / (1.f + expf(-v3));
            float cn = f_ * cs[p] + i_ * gg;
            float hn = o_ * tanhf(cn);
            cs[p] = cn;
            __half hr = __float2half(hn);
            nxth[b * Hdim + n0 + j] = hr;
            if (layer == 0) g_seq16[((size_t)t * 64 + b) * Hdim + n0 + j] = hr;
            if (t == Sq - 1) {
                g_h[layer][b * Hdim + n0 + j] = hn;
                g_c[layer][b * Hdim + n0 + j] = cn;
            }
        }
        __threadfence();
        __syncthreads();
        if (tid == 0) *(volatile unsigned*)&g_flag[cta] = F0 + 2 + t;
    }
}

// ---------------- finalize: pack output tuple (seq_last, h_n[2], c_n[2]) ----------------
__global__ void finalize_kernel(float* __restrict__ out, int out_size) {
    int idx = blockIdx.x * 256 + threadIdx.x;  // 0..65535
    const int N1 = Bq * Hdim;
    if (idx + 0 * N1 < out_size) out[idx]          = g_h[1][idx];  // seq[:, -1, :]
    if (idx + 1 * N1 < out_size) out[idx + N1]     = g_h[0][idx];  // h_n layer 0
    if (idx + 2 * N1 < out_size) out[idx + 2 * N1] = g_h[1][idx];  // h_n layer 1
    if (idx + 3 * N1 < out_size) out[idx + 3 * N1] = g_c[0][idx];  // c_n layer 0
    if (idx + 4 * N1 < out_size) out[idx + 4 * N1] = g_c[1][idx];  // c_n layer 1
}

// ---------------- launch: 6 graph nodes total ----------------
extern "C" void kernel_launch(void* const* d_in, const int* in_sizes, int n_in,
                              void* d_out, int out_size) {
    const float* x  = (const float*)d_in[0];
    const float* Wi = (const float*)d_in[1];
    const float* bi = (const float*)d_in[2];
    const float* Wh = (const float*)d_in[3];
    const float* bh = (const float*)d_in[4];
    float* out = (float*)d_out;
    (void)in_sizes; (void)n_in;

    const int recur_smem = 81920 + 132096 + 8448 + 4096 + 2048;  // 228608 B
    cudaFuncSetAttribute(recur_kernel, cudaFuncAttributeMaxDynamicSharedMemorySize,
                         recur_smem);

    prep_kernel<<<131072, 256>>>(Wi, Wh, x);
    for (int l = 0; l < 2; l++) {
        proj_kernel<<<dim3(NG / 64, NROWS / 128), 256>>>(l, bi, bh);
        recur_kernel<<<NCTA, 256, recur_smem>>>(l);
    }
    finalize_kernel<<<256, 256>>>(out, out_size);
}